// round 11
// baseline (speedup 1.0000x reference)
#include <cuda_runtime.h>
#include <cuda_fp16.h>
#include <float.h>
#include <stdint.h>

// Problem constants
#define B_   2
#define D_   64
#define N1_  16384
#define N2_  16384

#define BM 128
#define BN 128
#define NT (N2_/BN)      // 128
#define MT (N1_/BM)      // 128
#define GA 9             // A k-groups: 4 H + 4 L + 1 xyz/sq
#define GB 9             // B k-groups: 4 H + 4 L + 1 xyz/sq
#define NTH 256

// SMEM layout (bytes): A image + 2-deep B ring (BN=128 tiles)
#define ABYTES (GA*8*512)             // 36864
#define BBYTES (GB*8*512)             // 36864
#define B0_OFF ABYTES
#define SMEM_TOTAL (ABYTES + 2*BBYTES)  // 110592 -> 2 CTAs/SM
#define NCHB (BBYTES/16)              // 2304 chunks per B tile

// Scratch
__device__ float g_sq2[B_ * N2_];
__device__ float g_Asplit[(size_t)B_ * MT * GA * 8 * 128];
__device__ float g_Bsplit[(size_t)B_ * NT * GB * 8 * 128];

// ---------------------------------------------------------------------------
__device__ __forceinline__ uint16_t hi_h(float x) {
    return __half_as_ushort(__float2half_rn(x));
}
__device__ __forceinline__ uint16_t lo_h(float x) {
    __half h = __float2half_rn(x);
    return __half_as_ushort(__float2half_rn(x - __half2float(h)));
}
__device__ __forceinline__ uint16_t slotA(const float* P1, const float* X1,
                                          int ga, int sl, int m) {
    if (ga < 4)  return hi_h(P1[(size_t)(ga * 16 + sl) * N1_ + m]);
    if (ga < 8)  return lo_h(P1[(size_t)((ga - 4) * 16 + sl) * N1_ + m]);
    if (sl < 3)  return hi_h(X1[(size_t)sl * N1_ + m]);
    if (sl < 6)  return lo_h(X1[(size_t)(sl - 3) * N1_ + m]);
    if (sl < 9)  return hi_h(X1[(size_t)(sl - 6) * N1_ + m]);
    if (sl < 11) return 0x3C00;  // 1.0h (sq carriers)
    return 0;
}
__device__ __forceinline__ uint16_t slotB(const float* P2, const float* X2,
                                          const float* SQ, int gb, int sl, int n) {
    if (gb < 4)  return hi_h(P2[(size_t)(gb * 16 + sl) * N2_ + n]);
    if (gb < 8)  return lo_h(P2[(size_t)((gb - 4) * 16 + sl) * N2_ + n]);
    if (sl < 3)  return hi_h(X2[(size_t)sl * N2_ + n]);
    if (sl < 6)  return hi_h(X2[(size_t)(sl - 3) * N2_ + n]);
    if (sl < 9)  return lo_h(X2[(size_t)(sl - 6) * N2_ + n]);
    float v = -0.5f * SQ[n];
    if (sl == 9)  return hi_h(v);
    if (sl == 10) return lo_h(v);
    return 0;
}
__device__ __forceinline__ uint32_t packh(uint16_t a, uint16_t b) {
    return (uint32_t)a | ((uint32_t)b << 16);
}

#define MMA16(C, A, b0v, b1v)                                             \
  asm volatile("mma.sync.aligned.m16n8k16.row.col.f32.f16.f16.f32 "       \
    "{%0,%1,%2,%3}, {%4,%5,%6,%7}, {%8,%9}, {%0,%1,%2,%3};"               \
    : "+f"((C)[0]), "+f"((C)[1]), "+f"((C)[2]), "+f"((C)[3])              \
    : "r"((A).x), "r"((A).y), "r"((A).z), "r"((A).w), "r"(b0v), "r"(b1v))

__device__ __forceinline__ uint32_t smem_u32(const void* p) {
    uint32_t a;
    asm("{ .reg .u64 t; cvta.to.shared.u64 t, %1; cvt.u32.u64 %0, t; }" : "=r"(a) : "l"(p));
    return a;
}
__device__ __forceinline__ void cpa16(uint32_t s, const void* g) {
    asm volatile("cp.async.cg.shared.global [%0], [%1], 16;" :: "r"(s), "l"(g) : "memory");
}
#define CP_COMMIT() asm volatile("cp.async.commit_group;" ::: "memory")
#define CP_WAIT0()  asm volatile("cp.async.wait_group 0;" ::: "memory")

// ---------------------------------------------------------------------------
__global__ void sq2_kernel(const float* __restrict__ xyz2,
                           const float* __restrict__ points2) {
    int idx = blockIdx.x * blockDim.x + threadIdx.x;
    if (idx >= B_ * N2_) return;
    int b = idx / N2_, j = idx % N2_;
    const float* p = points2 + (size_t)b * D_ * N2_ + j;
    float s = 0.f;
    #pragma unroll
    for (int d = 0; d < D_; d++) { float v = p[(size_t)d * N2_]; s += v * v; }
    const float* x = xyz2 + (size_t)b * 3 * N2_ + j;
    #pragma unroll
    for (int d = 0; d < 3; d++) { float v = x[(size_t)d * N2_]; s += v * v; }
    g_sq2[idx] = s;
}

__global__ void prepA_kernel(const float* __restrict__ xyz1,
                             const float* __restrict__ points1) {
    int gw   = (blockIdx.x * blockDim.x + threadIdx.x) >> 5;
    int lane = threadIdx.x & 31;
    if (gw >= B_ * MT * GA * 8) return;
    int ab = gw % (GA * 8); int rem = gw / (GA * 8);
    int mt = rem % MT;      int b   = rem / MT;
    const float* P1 = points1 + (size_t)b * D_ * N1_;
    const float* X1 = xyz1    + (size_t)b * 3  * N1_;
    int ga = ab >> 3, fA = ab & 7;
    int lr = lane >> 2, lc = lane & 3;
    int m1 = mt * BM + fA * 16 + lr, m2 = m1 + 8;
    int s0 = 2 * lc;
    uint4 v;
    v.x = packh(slotA(P1, X1, ga, s0,     m1), slotA(P1, X1, ga, s0 + 1, m1));
    v.y = packh(slotA(P1, X1, ga, s0,     m2), slotA(P1, X1, ga, s0 + 1, m2));
    v.z = packh(slotA(P1, X1, ga, s0 + 8, m1), slotA(P1, X1, ga, s0 + 9, m1));
    v.w = packh(slotA(P1, X1, ga, s0 + 8, m2), slotA(P1, X1, ga, s0 + 9, m2));
    ((uint4*)g_Asplit)[(size_t)gw * 32 + lane] = v;
}

__global__ void prepB_kernel(const float* __restrict__ xyz2,
                             const float* __restrict__ points2) {
    int gw   = (blockIdx.x * blockDim.x + threadIdx.x) >> 5;
    int lane = threadIdx.x & 31;
    if (gw >= B_ * NT * GB * 8) return;
    int sb = gw % (GB * 8); int rem = gw / (GB * 8);
    int nt = rem % NT;      int b   = rem / NT;
    const float* P2 = points2 + (size_t)b * D_ * N2_;
    const float* X2 = xyz2    + (size_t)b * 3  * N2_;
    const float* SQ = g_sq2   + (size_t)b * N2_;
    int gb = sb >> 3, q = sb & 7;
    int lr = lane >> 2, lc = lane & 3;
    int n1 = nt * BN + q * 16 + lr, n2 = n1 + 8;
    int s0 = 2 * lc;
    uint4 v;
    v.x = packh(slotB(P2, X2, SQ, gb, s0,     n1), slotB(P2, X2, SQ, gb, s0 + 1, n1));
    v.y = packh(slotB(P2, X2, SQ, gb, s0 + 8, n1), slotB(P2, X2, SQ, gb, s0 + 9, n1));
    v.z = packh(slotB(P2, X2, SQ, gb, s0,     n2), slotB(P2, X2, SQ, gb, s0 + 1, n2));
    v.w = packh(slotB(P2, X2, SQ, gb, s0 + 8, n2), slotB(P2, X2, SQ, gb, s0 + 9, n2));
    ((uint4*)g_Bsplit)[(size_t)gw * 32 + lane] = v;
}

// ---------------------------------------------------------------------------
// Main: warp tile 32m x 64n, double-buffered B, CTA-phase-staggered tile order.
// ---------------------------------------------------------------------------
__global__ void __launch_bounds__(NTH, 2)
nn_mma_kernel(const float* __restrict__ xyz1, const float* __restrict__ xyz2,
              float* __restrict__ out) {
    extern __shared__ char smem[];
    const uint32_t su = smem_u32(smem);
    const int tid  = threadIdx.x;
    const int w    = tid >> 5, lane = tid & 31;
    const int wr   = w >> 1, wc = w & 1;       // 4m x 2n warp grid
    const int lr   = lane >> 2, lc = lane & 3;
    const int b    = blockIdx.y;
    const int mt   = blockIdx.x;
    const int m0   = mt * BM;
    // Phase stagger: co-resident CTAs (adjacent mt) start half a sweep apart
    const int phase = (mt & 1) * (NT / 2);

    const float* X1 = xyz1 + (size_t)b * 3 * N1_;
    const float* X2 = xyz2 + (size_t)b * 3 * N2_;

    // Prologue: A image + B tile 'phase'
    const float* gA = g_Asplit + (size_t)(b * MT + mt) * (GA * 8 * 128);
    for (int i = tid; i < ABYTES / 16; i += NTH) cpa16(su + i * 16, gA + i * 4);
    {
        const float* gB = g_Bsplit + (size_t)(b * NT + phase) * (GB * 8 * 128);
        for (int i = tid; i < NCHB; i += NTH) cpa16(su + B0_OFF + i * 16, gB + i * 4);
    }
    CP_COMMIT();
    CP_WAIT0();
    __syncthreads();

    float bestV[4] = {-FLT_MAX, -FLT_MAX, -FLT_MAX, -FLT_MAX};
    int   bestI[4] = {0x7FFFFFFF, 0x7FFFFFFF, 0x7FFFFFFF, 0x7FFFFFFF};

    const char* aB = smem + (size_t)lane * 16;

    for (int it = 0; it < NT; it++) {
        const int t  = (it + phase) & (NT - 1);      // actual tile index
        const int tn = (it + 1 + phase) & (NT - 1);  // next tile
        const int cur = it & 1;
        const char* bB = smem + B0_OFF + cur * BBYTES + (size_t)lane * 16;
        const uint32_t bufN = su + B0_OFF + (cur ^ 1) * BBYTES;
        const float* gB = g_Bsplit + (size_t)(b * NT + tn) * (GB * 8 * 128);
        const bool pf = (it + 1 < NT);

        float acc[2][8][4];
        #pragma unroll
        for (int f = 0; f < 2; f++)
            #pragma unroll
            for (int nf = 0; nf < 8; nf++)
                #pragma unroll
                for (int r = 0; r < 4; r++) acc[f][nf][r] = 0.f;

        // 4 point-dim groups with 3-term register reuse
        #pragma unroll
        for (int g = 0; g < 4; g++) {
            if (pf) {   // spread prefetch: 2 chunk-sets per group
                int i0 = (g * 2) * NTH + tid;
                if (i0 < NCHB) cpa16(bufN + i0 * 16, gB + i0 * 4);
                int i1 = (g * 2 + 1) * NTH + tid;
                if (i1 < NCHB) cpa16(bufN + i1 * 16, gB + i1 * 4);
            }
            // Phase 1: H.H
            uint4 aH0 = *(const uint4*)(aB + ((size_t)(g * 8 + wr * 2 + 0)) * 512);
            uint4 aH1 = *(const uint4*)(aB + ((size_t)(g * 8 + wr * 2 + 1)) * 512);
            uint4 bH0 = *(const uint4*)(bB + ((size_t)(g * 8 + wc * 4 + 0)) * 512);
            uint4 bH1 = *(const uint4*)(bB + ((size_t)(g * 8 + wc * 4 + 1)) * 512);
            uint4 bH2 = *(const uint4*)(bB + ((size_t)(g * 8 + wc * 4 + 2)) * 512);
            uint4 bH3 = *(const uint4*)(bB + ((size_t)(g * 8 + wc * 4 + 3)) * 512);
            MMA16(acc[0][0], aH0, bH0.x, bH0.y);
            MMA16(acc[0][1], aH0, bH0.z, bH0.w);
            MMA16(acc[0][2], aH0, bH1.x, bH1.y);
            MMA16(acc[0][3], aH0, bH1.z, bH1.w);
            MMA16(acc[0][4], aH0, bH2.x, bH2.y);
            MMA16(acc[0][5], aH0, bH2.z, bH2.w);
            MMA16(acc[0][6], aH0, bH3.x, bH3.y);
            MMA16(acc[0][7], aH0, bH3.z, bH3.w);
            MMA16(acc[1][0], aH1, bH0.x, bH0.y);
            MMA16(acc[1][1], aH1, bH0.z, bH0.w);
            MMA16(acc[1][2], aH1, bH1.x, bH1.y);
            MMA16(acc[1][3], aH1, bH1.z, bH1.w);
            MMA16(acc[1][4], aH1, bH2.x, bH2.y);
            MMA16(acc[1][5], aH1, bH2.z, bH2.w);
            MMA16(acc[1][6], aH1, bH3.x, bH3.y);
            MMA16(acc[1][7], aH1, bH3.z, bH3.w);
            // Phase 2: L.H
            uint4 aL0 = *(const uint4*)(aB + ((size_t)((4 + g) * 8 + wr * 2 + 0)) * 512);
            uint4 aL1 = *(const uint4*)(aB + ((size_t)((4 + g) * 8 + wr * 2 + 1)) * 512);
            MMA16(acc[0][0], aL0, bH0.x, bH0.y);
            MMA16(acc[0][1], aL0, bH0.z, bH0.w);
            MMA16(acc[0][2], aL0, bH1.x, bH1.y);
            MMA16(acc[0][3], aL0, bH1.z, bH1.w);
            MMA16(acc[0][4], aL0, bH2.x, bH2.y);
            MMA16(acc[0][5], aL0, bH2.z, bH2.w);
            MMA16(acc[0][6], aL0, bH3.x, bH3.y);
            MMA16(acc[0][7], aL0, bH3.z, bH3.w);
            MMA16(acc[1][0], aL1, bH0.x, bH0.y);
            MMA16(acc[1][1], aL1, bH0.z, bH0.w);
            MMA16(acc[1][2], aL1, bH1.x, bH1.y);
            MMA16(acc[1][3], aL1, bH1.z, bH1.w);
            MMA16(acc[1][4], aL1, bH2.x, bH2.y);
            MMA16(acc[1][5], aL1, bH2.z, bH2.w);
            MMA16(acc[1][6], aL1, bH3.x, bH3.y);
            MMA16(acc[1][7], aL1, bH3.z, bH3.w);
            // Phase 3: H.L
            uint4 bL0 = *(const uint4*)(bB + ((size_t)((4 + g) * 8 + wc * 4 + 0)) * 512);
            uint4 bL1 = *(const uint4*)(bB + ((size_t)((4 + g) * 8 + wc * 4 + 1)) * 512);
            uint4 bL2 = *(const uint4*)(bB + ((size_t)((4 + g) * 8 + wc * 4 + 2)) * 512);
            uint4 bL3 = *(const uint4*)(bB + ((size_t)((4 + g) * 8 + wc * 4 + 3)) * 512);
            MMA16(acc[0][0], aH0, bL0.x, bL0.y);
            MMA16(acc[0][1], aH0, bL0.z, bL0.w);
            MMA16(acc[0][2], aH0, bL1.x, bL1.y);
            MMA16(acc[0][3], aH0, bL1.z, bL1.w);
            MMA16(acc[0][4], aH0, bL2.x, bL2.y);
            MMA16(acc[0][5], aH0, bL2.z, bL2.w);
            MMA16(acc[0][6], aH0, bL3.x, bL3.y);
            MMA16(acc[0][7], aH0, bL3.z, bL3.w);
            MMA16(acc[1][0], aH1, bL0.x, bL0.y);
            MMA16(acc[1][1], aH1, bL0.z, bL0.w);
            MMA16(acc[1][2], aH1, bL1.x, bL1.y);
            MMA16(acc[1][3], aH1, bL1.z, bL1.w);
            MMA16(acc[1][4], aH1, bL2.x, bL2.y);
            MMA16(acc[1][5], aH1, bL2.z, bL2.w);
            MMA16(acc[1][6], aH1, bL3.x, bL3.y);
            MMA16(acc[1][7], aH1, bL3.z, bL3.w);
        }
        // xyz + sq group
        {
            if (pf) {
                int i0 = 8 * NTH + tid;
                if (i0 < NCHB) cpa16(bufN + i0 * 16, gB + i0 * 4);
                int i1 = 9 * NTH + tid;
                if (i1 < NCHB) cpa16(bufN + i1 * 16, gB + i1 * 4);
            }
            uint4 a0 = *(const uint4*)(aB + ((size_t)(64 + wr * 2 + 0)) * 512);
            uint4 a1 = *(const uint4*)(aB + ((size_t)(64 + wr * 2 + 1)) * 512);
            uint4 b0 = *(const uint4*)(bB + ((size_t)(64 + wc * 4 + 0)) * 512);
            uint4 b1 = *(const uint4*)(bB + ((size_t)(64 + wc * 4 + 1)) * 512);
            uint4 b2 = *(const uint4*)(bB + ((size_t)(64 + wc * 4 + 2)) * 512);
            uint4 b3 = *(const uint4*)(bB + ((size_t)(64 + wc * 4 + 3)) * 512);
            MMA16(acc[0][0], a0, b0.x, b0.y);
            MMA16(acc[0][1], a0, b0.z, b0.w);
            MMA16(acc[0][2], a0, b1.x, b1.y);
            MMA16(acc[0][3], a0, b1.z, b1.w);
            MMA16(acc[0][4], a0, b2.x, b2.y);
            MMA16(acc[0][5], a0, b2.z, b2.w);
            MMA16(acc[0][6], a0, b3.x, b3.y);
            MMA16(acc[0][7], a0, b3.z, b3.w);
            MMA16(acc[1][0], a1, b0.x, b0.y);
            MMA16(acc[1][1], a1, b0.z, b0.w);
            MMA16(acc[1][2], a1, b1.x, b1.y);
            MMA16(acc[1][3], a1, b1.z, b1.w);
            MMA16(acc[1][4], a1, b2.x, b2.y);
            MMA16(acc[1][5], a1, b2.z, b2.w);
            MMA16(acc[1][6], a1, b3.x, b3.y);
            MMA16(acc[1][7], a1, b3.z, b3.w);
        }
        if (pf) CP_COMMIT();

        // Epilogue: tile-order-independent argmax with smallest-j tie-break.
        #pragma unroll
        for (int f = 0; f < 2; f++)
            #pragma unroll
            for (int h = 0; h < 2; h++) {
                const int bi = f * 2 + h;
                float m = acc[f][0][h * 2];
                #pragma unroll
                for (int nf = 0; nf < 8; nf++) {
                    m = fmaxf(m, acc[f][nf][h * 2]);
                    m = fmaxf(m, acc[f][nf][h * 2 + 1]);
                }
                if (m >= bestV[bi]) {         // rare slow path
                    int jj = 0;
                    #pragma unroll
                    for (int nf = 7; nf >= 0; nf--)
                        #pragma unroll
                        for (int c = 1; c >= 0; c--)
                            if (acc[f][nf][h * 2 + c] == m)
                                jj = t * BN + wc * 64 + nf * 8 + 2 * lc + c;
                    if (m > bestV[bi] || jj < bestI[bi]) {
                        bestV[bi] = m; bestI[bi] = jj;
                    }
                }
            }

        CP_WAIT0();
        __syncthreads();
    }

    // Lane reduction across lc
    #pragma unroll
    for (int off = 1; off <= 2; off <<= 1) {
        #pragma unroll
        for (int r = 0; r < 4; r++) {
            float ov = __shfl_xor_sync(0xffffffff, bestV[r], off);
            int   oi = __shfl_xor_sync(0xffffffff, bestI[r], off);
            if (ov > bestV[r] || (ov == bestV[r] && oi < bestI[r])) {
                bestV[r] = ov; bestI[r] = oi;
            }
        }
    }
    __syncthreads();
    float* sv = (float*)smem;
    int*   si = (int*)(smem + 128 * 2 * 4);
    if (lc == 0) {
        #pragma unroll
        for (int r = 0; r < 4; r++) {
            int row = wr * 32 + (r >> 1) * 16 + lr + (r & 1) * 8;
            sv[row * 2 + wc] = bestV[r];
            si[row * 2 + wc] = bestI[r];
        }
    }
    __syncthreads();

    if (tid < BM) {
        float v0 = sv[tid * 2], v1 = sv[tid * 2 + 1];
        int   i0 = si[tid * 2], i1 = si[tid * 2 + 1];
        int   bi = (v1 > v0 || (v1 == v0 && i1 < i0)) ? i1 : i0;
        int   gi = m0 + tid;
        out[b * N1_ + gi]        = (float)gi;
        out[(B_ + b) * N1_ + gi] = (float)bi;
        float* dir = out + 2 * B_ * N1_;
        #pragma unroll
        for (int d = 0; d < 3; d++)
            dir[((size_t)b * 3 + d) * N1_ + gi] =
                X2[(size_t)d * N2_ + bi] - X1[(size_t)d * N1_ + gi];
    }
}

// ---------------------------------------------------------------------------
extern "C" void kernel_launch(void* const* d_in, const int* in_sizes, int n_in,
                              void* d_out, int out_size) {
    const float* xyz1    = (const float*)d_in[0];
    const float* xyz2    = (const float*)d_in[1];
    const float* points1 = (const float*)d_in[2];
    const float* points2 = (const float*)d_in[3];
    float* out = (float*)d_out;

    sq2_kernel<<<(B_ * N2_ + 255) / 256, 256>>>(xyz2, points2);
    {
        int warpsA = B_ * MT * GA * 8;
        prepA_kernel<<<(warpsA * 32 + NTH - 1) / NTH, NTH>>>(xyz1, points1);
        int warpsB = B_ * NT * GB * 8;
        prepB_kernel<<<(warpsB * 32 + NTH - 1) / NTH, NTH>>>(xyz2, points2);
    }

    cudaFuncSetAttribute(nn_mma_kernel,
                         cudaFuncAttributeMaxDynamicSharedMemorySize,
                         SMEM_TOTAL);
    dim3 grid(MT, B_);
    nn_mma_kernel<<<grid, NTH, SMEM_TOTAL>>>(xyz1, xyz2, out);
}

// round 12
// speedup vs baseline: 1.1475x; 1.1475x over previous
#include <cuda_runtime.h>
#include <cuda_fp16.h>
#include <float.h>
#include <stdint.h>

// Problem constants
#define B_   2
#define D_   64
#define N1_  16384
#define N2_  16384

#define BM 128
#define BN 128
#define NT (N2_/BN)      // 128
#define MT (N1_/BM)      // 128
#define S_  4            // N2-sweep split factor (load balance)
#define TPS (NT/S_)      // 32 tiles per work unit
#define GA 9             // A k-groups: 4 H + 4 L + 1 xyz/sq
#define GB 9             // B k-groups: 4 H + 4 L + 1 xyz/sq
#define NTH 256

// SMEM layout (bytes): A image + 2-deep B ring
#define ABYTES (GA*8*512)             // 36864
#define BBYTES (GB*8*512)             // 36864
#define B0_OFF ABYTES
#define SMEM_TOTAL (ABYTES + 2*BBYTES)  // 110592 -> 2 CTAs/SM
#define NCHB (BBYTES/16)              // 2304 chunks per B tile

// Scratch
__device__ float g_sq2[B_ * N2_];
__device__ float g_Asplit[(size_t)B_ * MT * GA * 8 * 128];
__device__ float g_Bsplit[(size_t)B_ * NT * GB * 8 * 128];
__device__ unsigned long long g_part[B_ * S_ * N1_];   // packed (val|~idx)

// ---------------------------------------------------------------------------
__device__ __forceinline__ uint16_t hi_h(float x) {
    return __half_as_ushort(__float2half_rn(x));
}
__device__ __forceinline__ uint16_t lo_h(float x) {
    __half h = __float2half_rn(x);
    return __half_as_ushort(__float2half_rn(x - __half2float(h)));
}
__device__ __forceinline__ uint16_t slotA(const float* P1, const float* X1,
                                          int ga, int sl, int m) {
    if (ga < 4)  return hi_h(P1[(size_t)(ga * 16 + sl) * N1_ + m]);
    if (ga < 8)  return lo_h(P1[(size_t)((ga - 4) * 16 + sl) * N1_ + m]);
    if (sl < 3)  return hi_h(X1[(size_t)sl * N1_ + m]);
    if (sl < 6)  return lo_h(X1[(size_t)(sl - 3) * N1_ + m]);
    if (sl < 9)  return hi_h(X1[(size_t)(sl - 6) * N1_ + m]);
    if (sl < 11) return 0x3C00;  // 1.0h (sq carriers)
    return 0;
}
__device__ __forceinline__ uint16_t slotB(const float* P2, const float* X2,
                                          const float* SQ, int gb, int sl, int n) {
    if (gb < 4)  return hi_h(P2[(size_t)(gb * 16 + sl) * N2_ + n]);
    if (gb < 8)  return lo_h(P2[(size_t)((gb - 4) * 16 + sl) * N2_ + n]);
    if (sl < 3)  return hi_h(X2[(size_t)sl * N2_ + n]);
    if (sl < 6)  return hi_h(X2[(size_t)(sl - 3) * N2_ + n]);
    if (sl < 9)  return lo_h(X2[(size_t)(sl - 6) * N2_ + n]);
    float v = -0.5f * SQ[n];
    if (sl == 9)  return hi_h(v);
    if (sl == 10) return lo_h(v);
    return 0;
}
__device__ __forceinline__ uint32_t packh(uint16_t a, uint16_t b) {
    return (uint32_t)a | ((uint32_t)b << 16);
}

#define MMA16(C, A, b0v, b1v)                                             \
  asm volatile("mma.sync.aligned.m16n8k16.row.col.f32.f16.f16.f32 "       \
    "{%0,%1,%2,%3}, {%4,%5,%6,%7}, {%8,%9}, {%0,%1,%2,%3};"               \
    : "+f"((C)[0]), "+f"((C)[1]), "+f"((C)[2]), "+f"((C)[3])              \
    : "r"((A).x), "r"((A).y), "r"((A).z), "r"((A).w), "r"(b0v), "r"(b1v))

__device__ __forceinline__ uint32_t smem_u32(const void* p) {
    uint32_t a;
    asm("{ .reg .u64 t; cvta.to.shared.u64 t, %1; cvt.u32.u64 %0, t; }" : "=r"(a) : "l"(p));
    return a;
}
__device__ __forceinline__ void cpa16(uint32_t s, const void* g) {
    asm volatile("cp.async.cg.shared.global [%0], [%1], 16;" :: "r"(s), "l"(g) : "memory");
}
#define CP_COMMIT() asm volatile("cp.async.commit_group;" ::: "memory")
#define CP_WAIT0()  asm volatile("cp.async.wait_group 0;" ::: "memory")

// ---------------------------------------------------------------------------
__global__ void sq2_kernel(const float* __restrict__ xyz2,
                           const float* __restrict__ points2) {
    int idx = blockIdx.x * blockDim.x + threadIdx.x;
    if (idx >= B_ * N2_) return;
    int b = idx / N2_, j = idx % N2_;
    const float* p = points2 + (size_t)b * D_ * N2_ + j;
    float s = 0.f;
    #pragma unroll
    for (int d = 0; d < D_; d++) { float v = p[(size_t)d * N2_]; s += v * v; }
    const float* x = xyz2 + (size_t)b * 3 * N2_ + j;
    #pragma unroll
    for (int d = 0; d < 3; d++) { float v = x[(size_t)d * N2_]; s += v * v; }
    g_sq2[idx] = s;
}

__global__ void prepA_kernel(const float* __restrict__ xyz1,
                             const float* __restrict__ points1) {
    int gw   = (blockIdx.x * blockDim.x + threadIdx.x) >> 5;
    int lane = threadIdx.x & 31;
    if (gw >= B_ * MT * GA * 8) return;
    int ab = gw % (GA * 8); int rem = gw / (GA * 8);
    int mt = rem % MT;      int b   = rem / MT;
    const float* P1 = points1 + (size_t)b * D_ * N1_;
    const float* X1 = xyz1    + (size_t)b * 3  * N1_;
    int ga = ab >> 3, fA = ab & 7;
    int lr = lane >> 2, lc = lane & 3;
    int m1 = mt * BM + fA * 16 + lr, m2 = m1 + 8;
    int s0 = 2 * lc;
    uint4 v;
    v.x = packh(slotA(P1, X1, ga, s0,     m1), slotA(P1, X1, ga, s0 + 1, m1));
    v.y = packh(slotA(P1, X1, ga, s0,     m2), slotA(P1, X1, ga, s0 + 1, m2));
    v.z = packh(slotA(P1, X1, ga, s0 + 8, m1), slotA(P1, X1, ga, s0 + 9, m1));
    v.w = packh(slotA(P1, X1, ga, s0 + 8, m2), slotA(P1, X1, ga, s0 + 9, m2));
    ((uint4*)g_Asplit)[(size_t)gw * 32 + lane] = v;
}

__global__ void prepB_kernel(const float* __restrict__ xyz2,
                             const float* __restrict__ points2) {
    int gw   = (blockIdx.x * blockDim.x + threadIdx.x) >> 5;
    int lane = threadIdx.x & 31;
    if (gw >= B_ * NT * GB * 8) return;
    int sb = gw % (GB * 8); int rem = gw / (GB * 8);
    int nt = rem % NT;      int b   = rem / NT;
    const float* P2 = points2 + (size_t)b * D_ * N2_;
    const float* X2 = xyz2    + (size_t)b * 3  * N2_;
    const float* SQ = g_sq2   + (size_t)b * N2_;
    int gb = sb >> 3, q = sb & 7;
    int lr = lane >> 2, lc = lane & 3;
    int n1 = nt * BN + q * 16 + lr, n2 = n1 + 8;
    int s0 = 2 * lc;
    uint4 v;
    v.x = packh(slotB(P2, X2, SQ, gb, s0,     n1), slotB(P2, X2, SQ, gb, s0 + 1, n1));
    v.y = packh(slotB(P2, X2, SQ, gb, s0 + 8, n1), slotB(P2, X2, SQ, gb, s0 + 9, n1));
    v.z = packh(slotB(P2, X2, SQ, gb, s0,     n2), slotB(P2, X2, SQ, gb, s0 + 1, n2));
    v.w = packh(slotB(P2, X2, SQ, gb, s0 + 8, n2), slotB(P2, X2, SQ, gb, s0 + 9, n2));
    ((uint4*)g_Bsplit)[(size_t)gw * 32 + lane] = v;
}

// ---------------------------------------------------------------------------
// Main: warp tile 32m x 64n; each CTA sweeps TPS tiles, writes packed partial.
// ---------------------------------------------------------------------------
__global__ void __launch_bounds__(NTH, 2)
nn_mma_kernel(float* __restrict__ unused_out) {
    extern __shared__ char smem[];
    const uint32_t su = smem_u32(smem);
    const int tid  = threadIdx.x;
    const int w    = tid >> 5, lane = tid & 31;
    const int wr   = w >> 1, wc = w & 1;       // 4m x 2n warp grid
    const int lr   = lane >> 2, lc = lane & 3;
    const int b    = blockIdx.y;
    const int mt   = blockIdx.x % MT;
    const int s    = blockIdx.x / MT;          // N2-chunk index
    const int m0   = mt * BM;
    const int t0   = s * TPS;

    // Prologue: A image + B tile t0
    const float* gA = g_Asplit + (size_t)(b * MT + mt) * (GA * 8 * 128);
    for (int i = tid; i < ABYTES / 16; i += NTH) cpa16(su + i * 16, gA + i * 4);
    {
        const float* gB = g_Bsplit + (size_t)(b * NT + t0) * (GB * 8 * 128);
        for (int i = tid; i < NCHB; i += NTH) cpa16(su + B0_OFF + i * 16, gB + i * 4);
    }
    CP_COMMIT();
    CP_WAIT0();
    __syncthreads();

    float bestV[4] = {-FLT_MAX, -FLT_MAX, -FLT_MAX, -FLT_MAX};
    int   bestI[4] = {0, 0, 0, 0};

    const char* aB = smem + (size_t)lane * 16;

    for (int it = 0; it < TPS; it++) {
        const int t = t0 + it;
        const int cur = it & 1;
        const char* bB = smem + B0_OFF + cur * BBYTES + (size_t)lane * 16;
        const uint32_t bufN = su + B0_OFF + (cur ^ 1) * BBYTES;
        const float* gB = g_Bsplit + (size_t)(b * NT + t + 1) * (GB * 8 * 128);
        const bool pf = (it + 1 < TPS);

        float acc[2][8][4];
        #pragma unroll
        for (int f = 0; f < 2; f++)
            #pragma unroll
            for (int nf = 0; nf < 8; nf++)
                #pragma unroll
                for (int r = 0; r < 4; r++) acc[f][nf][r] = 0.f;

        // 4 point-dim groups with 3-term register reuse
        #pragma unroll
        for (int g = 0; g < 4; g++) {
            if (pf) {   // spread prefetch: 2 chunk-sets per group
                int i0 = (g * 2) * NTH + tid;
                if (i0 < NCHB) cpa16(bufN + i0 * 16, gB + i0 * 4);
                int i1 = (g * 2 + 1) * NTH + tid;
                if (i1 < NCHB) cpa16(bufN + i1 * 16, gB + i1 * 4);
            }
            // Phase 1: H.H
            uint4 aH0 = *(const uint4*)(aB + ((size_t)(g * 8 + wr * 2 + 0)) * 512);
            uint4 aH1 = *(const uint4*)(aB + ((size_t)(g * 8 + wr * 2 + 1)) * 512);
            uint4 bH0 = *(const uint4*)(bB + ((size_t)(g * 8 + wc * 4 + 0)) * 512);
            uint4 bH1 = *(const uint4*)(bB + ((size_t)(g * 8 + wc * 4 + 1)) * 512);
            uint4 bH2 = *(const uint4*)(bB + ((size_t)(g * 8 + wc * 4 + 2)) * 512);
            uint4 bH3 = *(const uint4*)(bB + ((size_t)(g * 8 + wc * 4 + 3)) * 512);
            MMA16(acc[0][0], aH0, bH0.x, bH0.y);
            MMA16(acc[0][1], aH0, bH0.z, bH0.w);
            MMA16(acc[0][2], aH0, bH1.x, bH1.y);
            MMA16(acc[0][3], aH0, bH1.z, bH1.w);
            MMA16(acc[0][4], aH0, bH2.x, bH2.y);
            MMA16(acc[0][5], aH0, bH2.z, bH2.w);
            MMA16(acc[0][6], aH0, bH3.x, bH3.y);
            MMA16(acc[0][7], aH0, bH3.z, bH3.w);
            MMA16(acc[1][0], aH1, bH0.x, bH0.y);
            MMA16(acc[1][1], aH1, bH0.z, bH0.w);
            MMA16(acc[1][2], aH1, bH1.x, bH1.y);
            MMA16(acc[1][3], aH1, bH1.z, bH1.w);
            MMA16(acc[1][4], aH1, bH2.x, bH2.y);
            MMA16(acc[1][5], aH1, bH2.z, bH2.w);
            MMA16(acc[1][6], aH1, bH3.x, bH3.y);
            MMA16(acc[1][7], aH1, bH3.z, bH3.w);
            // Phase 2: L.H
            uint4 aL0 = *(const uint4*)(aB + ((size_t)((4 + g) * 8 + wr * 2 + 0)) * 512);
            uint4 aL1 = *(const uint4*)(aB + ((size_t)((4 + g) * 8 + wr * 2 + 1)) * 512);
            MMA16(acc[0][0], aL0, bH0.x, bH0.y);
            MMA16(acc[0][1], aL0, bH0.z, bH0.w);
            MMA16(acc[0][2], aL0, bH1.x, bH1.y);
            MMA16(acc[0][3], aL0, bH1.z, bH1.w);
            MMA16(acc[0][4], aL0, bH2.x, bH2.y);
            MMA16(acc[0][5], aL0, bH2.z, bH2.w);
            MMA16(acc[0][6], aL0, bH3.x, bH3.y);
            MMA16(acc[0][7], aL0, bH3.z, bH3.w);
            MMA16(acc[1][0], aL1, bH0.x, bH0.y);
            MMA16(acc[1][1], aL1, bH0.z, bH0.w);
            MMA16(acc[1][2], aL1, bH1.x, bH1.y);
            MMA16(acc[1][3], aL1, bH1.z, bH1.w);
            MMA16(acc[1][4], aL1, bH2.x, bH2.y);
            MMA16(acc[1][5], aL1, bH2.z, bH2.w);
            MMA16(acc[1][6], aL1, bH3.x, bH3.y);
            MMA16(acc[1][7], aL1, bH3.z, bH3.w);
            // Phase 3: H.L
            uint4 bL0 = *(const uint4*)(bB + ((size_t)((4 + g) * 8 + wc * 4 + 0)) * 512);
            uint4 bL1 = *(const uint4*)(bB + ((size_t)((4 + g) * 8 + wc * 4 + 1)) * 512);
            uint4 bL2 = *(const uint4*)(bB + ((size_t)((4 + g) * 8 + wc * 4 + 2)) * 512);
            uint4 bL3 = *(const uint4*)(bB + ((size_t)((4 + g) * 8 + wc * 4 + 3)) * 512);
            MMA16(acc[0][0], aH0, bL0.x, bL0.y);
            MMA16(acc[0][1], aH0, bL0.z, bL0.w);
            MMA16(acc[0][2], aH0, bL1.x, bL1.y);
            MMA16(acc[0][3], aH0, bL1.z, bL1.w);
            MMA16(acc[0][4], aH0, bL2.x, bL2.y);
            MMA16(acc[0][5], aH0, bL2.z, bL2.w);
            MMA16(acc[0][6], aH0, bL3.x, bL3.y);
            MMA16(acc[0][7], aH0, bL3.z, bL3.w);
            MMA16(acc[1][0], aH1, bL0.x, bL0.y);
            MMA16(acc[1][1], aH1, bL0.z, bL0.w);
            MMA16(acc[1][2], aH1, bL1.x, bL1.y);
            MMA16(acc[1][3], aH1, bL1.z, bL1.w);
            MMA16(acc[1][4], aH1, bL2.x, bL2.y);
            MMA16(acc[1][5], aH1, bL2.z, bL2.w);
            MMA16(acc[1][6], aH1, bL3.x, bL3.y);
            MMA16(acc[1][7], aH1, bL3.z, bL3.w);
        }
        // xyz + sq group
        {
            if (pf) {
                int i0 = 8 * NTH + tid;
                if (i0 < NCHB) cpa16(bufN + i0 * 16, gB + i0 * 4);
                int i1 = 9 * NTH + tid;
                if (i1 < NCHB) cpa16(bufN + i1 * 16, gB + i1 * 4);
            }
            uint4 a0 = *(const uint4*)(aB + ((size_t)(64 + wr * 2 + 0)) * 512);
            uint4 a1 = *(const uint4*)(aB + ((size_t)(64 + wr * 2 + 1)) * 512);
            uint4 b0 = *(const uint4*)(bB + ((size_t)(64 + wc * 4 + 0)) * 512);
            uint4 b1 = *(const uint4*)(bB + ((size_t)(64 + wc * 4 + 1)) * 512);
            uint4 b2 = *(const uint4*)(bB + ((size_t)(64 + wc * 4 + 2)) * 512);
            uint4 b3 = *(const uint4*)(bB + ((size_t)(64 + wc * 4 + 3)) * 512);
            MMA16(acc[0][0], a0, b0.x, b0.y);
            MMA16(acc[0][1], a0, b0.z, b0.w);
            MMA16(acc[0][2], a0, b1.x, b1.y);
            MMA16(acc[0][3], a0, b1.z, b1.w);
            MMA16(acc[0][4], a0, b2.x, b2.y);
            MMA16(acc[0][5], a0, b2.z, b2.w);
            MMA16(acc[0][6], a0, b3.x, b3.y);
            MMA16(acc[0][7], a0, b3.z, b3.w);
            MMA16(acc[1][0], a1, b0.x, b0.y);
            MMA16(acc[1][1], a1, b0.z, b0.w);
            MMA16(acc[1][2], a1, b1.x, b1.y);
            MMA16(acc[1][3], a1, b1.z, b1.w);
            MMA16(acc[1][4], a1, b2.x, b2.y);
            MMA16(acc[1][5], a1, b2.z, b2.w);
            MMA16(acc[1][6], a1, b3.x, b3.y);
            MMA16(acc[1][7], a1, b3.z, b3.w);
        }
        if (pf) CP_COMMIT();

        // Epilogue: per-row max tree + rare index recovery (j ascending)
        #pragma unroll
        for (int f = 0; f < 2; f++)
            #pragma unroll
            for (int h = 0; h < 2; h++) {
                const int bi = f * 2 + h;
                float m = acc[f][0][h * 2];
                #pragma unroll
                for (int nf = 0; nf < 8; nf++) {
                    m = fmaxf(m, acc[f][nf][h * 2]);
                    m = fmaxf(m, acc[f][nf][h * 2 + 1]);
                }
                if (m > bestV[bi]) {
                    bestV[bi] = m;
                    int jj = 0;
                    #pragma unroll
                    for (int nf = 7; nf >= 0; nf--)
                        #pragma unroll
                        for (int c = 1; c >= 0; c--)
                            if (acc[f][nf][h * 2 + c] == m)
                                jj = t * BN + wc * 64 + nf * 8 + 2 * lc + c;
                    bestI[bi] = jj;   // descending scan => smallest j wins
                }
            }

        CP_WAIT0();
        __syncthreads();
    }

    // Lane reduction across lc
    #pragma unroll
    for (int off = 1; off <= 2; off <<= 1) {
        #pragma unroll
        for (int r = 0; r < 4; r++) {
            float ov = __shfl_xor_sync(0xffffffff, bestV[r], off);
            int   oi = __shfl_xor_sync(0xffffffff, bestI[r], off);
            if (ov > bestV[r] || (ov == bestV[r] && oi < bestI[r])) {
                bestV[r] = ov; bestI[r] = oi;
            }
        }
    }
    __syncthreads();
    float* sv = (float*)smem;
    int*   si = (int*)(smem + 128 * 2 * 4);
    if (lc == 0) {
        #pragma unroll
        for (int r = 0; r < 4; r++) {
            int row = wr * 32 + (r >> 1) * 16 + lr + (r & 1) * 8;
            sv[row * 2 + wc] = bestV[r];
            si[row * 2 + wc] = bestI[r];
        }
    }
    __syncthreads();

    if (tid < BM) {
        float v0 = sv[tid * 2], v1 = sv[tid * 2 + 1];
        int   i0 = si[tid * 2], i1 = si[tid * 2 + 1];
        float v = v0; int i = i0;
        if (v1 > v0 || (v1 == v0 && i1 < i0)) { v = v1; i = i1; }
        // Pack: sortable-float (sign-flip trick) | ~idx  -> max == (max v, min i)
        uint32_t u = __float_as_uint(v);
        u = (u & 0x80000000u) ? ~u : (u | 0x80000000u);
        unsigned long long p =
            ((unsigned long long)u << 32) | (uint32_t)(0xFFFFFFFFu ^ (uint32_t)i);
        g_part[(b * S_ + s) * N1_ + m0 + tid] = p;
    }
}

// ---------------------------------------------------------------------------
// Finalize: merge S_ partials per row, emit corres + direction.
// ---------------------------------------------------------------------------
__global__ void finalize_kernel(const float* __restrict__ xyz1,
                                const float* __restrict__ xyz2,
                                float* __restrict__ out) {
    int idx = blockIdx.x * blockDim.x + threadIdx.x;
    if (idx >= B_ * N1_) return;
    int b = idx / N1_, gi = idx % N1_;
    unsigned long long best = 0;
    #pragma unroll
    for (int s = 0; s < S_; s++) {
        unsigned long long p = g_part[(b * S_ + s) * N1_ + gi];
        if (p > best) best = p;
    }
    int bi = (int)(0xFFFFFFFFu ^ (uint32_t)(best & 0xFFFFFFFFull));
    const float* X1 = xyz1 + (size_t)b * 3 * N1_;
    const float* X2 = xyz2 + (size_t)b * 3 * N2_;
    out[b * N1_ + gi]        = (float)gi;
    out[(B_ + b) * N1_ + gi] = (float)bi;
    float* dir = out + 2 * B_ * N1_;
    #pragma unroll
    for (int d = 0; d < 3; d++)
        dir[((size_t)b * 3 + d) * N1_ + gi] =
            X2[(size_t)d * N2_ + bi] - X1[(size_t)d * N1_ + gi];
}

// ---------------------------------------------------------------------------
extern "C" void kernel_launch(void* const* d_in, const int* in_sizes, int n_in,
                              void* d_out, int out_size) {
    const float* xyz1    = (const float*)d_in[0];
    const float* xyz2    = (const float*)d_in[1];
    const float* points1 = (const float*)d_in[2];
    const float* points2 = (const float*)d_in[3];
    float* out = (float*)d_out;

    sq2_kernel<<<(B_ * N2_ + 255) / 256, 256>>>(xyz2, points2);
    {
        int warpsA = B_ * MT * GA * 8;
        prepA_kernel<<<(warpsA * 32 + NTH - 1) / NTH, NTH>>>(xyz1, points1);
        int warpsB = B_ * NT * GB * 8;
        prepB_kernel<<<(warpsB * 32 + NTH - 1) / NTH, NTH>>>(xyz2, points2);
    }

    cudaFuncSetAttribute(nn_mma_kernel,
                         cudaFuncAttributeMaxDynamicSharedMemorySize,
                         SMEM_TOTAL);
    dim3 grid(MT * S_, B_);
    nn_mma_kernel<<<grid, NTH, SMEM_TOTAL>>>(out);

    finalize_kernel<<<(B_ * N1_ + 255) / 256, 256>>>(xyz1, xyz2, out);
}